// round 15
// baseline (speedup 1.0000x reference)
#include <cuda_runtime.h>
#include <cuda_fp16.h>
#include <cstdint>

#define NROWS 8192
#define DIM   2048
#define VOCAB 32000
#define TOPK  5
#define CAND  8
#define LOCK  8
#define ALPHA 0.5f
#define TEMP  10.0f

// GEMM tiling (f16): CTA 128x256, k-tile 64 halfs (=128B rows)
#define BM    128
#define BN    256
#define BK    64
#define NKT   (DIM / BK)            // 32
#define NSTG  4
#define NCT   (VOCAB / BN)          // 125 col tiles (segments)
#define A_BYTES (BM * 128)
#define B_BYTES (BN * 128)
#define STG_BYTES (A_BYTES + B_BYTES)
#define GEMM_SMEM (NSTG * STG_BYTES)   // 192 KB

// ---------------- device scratch ----------------
__device__ __half g_embh[(size_t)NROWS * DIM];
__device__ __half g_voch[(size_t)VOCAB * DIM];     // vocab * inv_norm
__device__ __half g_simh[(size_t)NROWS * VOCAB];   // f16 screen sims
__device__ float  g_rmax[(size_t)NROWS * NCT];     // per-row per-segment max
__device__ float  g_emb_inv[NROWS];
__device__ float  g_voc_inv[VOCAB];

// ---------------- helpers ----------------
__device__ __forceinline__ uint32_t smem_u32(const void* p) {
    uint32_t a;
    asm("{ .reg .u64 t; cvta.to.shared.u64 t, %1; cvt.u32.u64 %0, t; }" : "=r"(a) : "l"(p));
    return a;
}
#define CP16(dst_u32, src_ptr) \
    asm volatile("cp.async.cg.shared.global [%0], [%1], 16;" \
        :: "r"(dst_u32), "l"((unsigned long long)__cvta_generic_to_global((const void*)(src_ptr))) : "memory")
#define CP_COMMIT() asm volatile("cp.async.commit_group;" ::: "memory")
#define CP_WAIT(n)  asm volatile("cp.async.wait_group %0;" :: "n"(n) : "memory")

__device__ __forceinline__ void ldsm4(uint32_t& d0, uint32_t& d1, uint32_t& d2, uint32_t& d3,
                                      uint32_t addr) {
    asm volatile("ldmatrix.sync.aligned.m8n8.x4.shared.b16 {%0,%1,%2,%3}, [%4];"
                 : "=r"(d0), "=r"(d1), "=r"(d2), "=r"(d3) : "r"(addr));
}
// f16 inputs, f16 accumulate
#define MMA16816F16(d, a, b) \
    asm volatile("mma.sync.aligned.m16n8k16.row.col.f16.f16.f16.f16 " \
        "{%0,%1}, {%2,%3,%4,%5}, {%6,%7}, {%0,%1};" \
        : "+r"((d)[0]), "+r"((d)[1]) \
        : "r"((a)[0]), "r"((a)[1]), "r"((a)[2]), "r"((a)[3]), "r"((b)[0]), "r"((b)[1]))

// lexicographic better: higher val, tie -> smaller col (fully deterministic)
__device__ __forceinline__ bool better(float v, int c, float v2, int c2) {
    return (v > v2) || (v == v2 && c < c2);
}

// ---------------- fused prep: norms + f16 conversion -------------------------
// blocks [0, NROWS): emb rows; blocks [NROWS, NROWS+VOCAB): vocab rows
__global__ void __launch_bounds__(256) prep_kernel(const float* __restrict__ emb,
                                                   const float* __restrict__ voc) {
    int b = blockIdx.x;
    int t = threadIdx.x;
    int lane = t & 31;
    int wq = t >> 5;
    bool is_emb = (b < NROWS);
    int row = is_emb ? b : (b - NROWS);
    const float* src = is_emb ? (emb + (size_t)row * DIM) : (voc + (size_t)row * DIM);

    const float4* s4 = (const float4*)src;
    float4 a = s4[t * 2], bb = s4[t * 2 + 1];
    float ss = a.x*a.x + a.y*a.y + a.z*a.z + a.w*a.w
             + bb.x*bb.x + bb.y*bb.y + bb.z*bb.z + bb.w*bb.w;
    // warp reduce, then 8-wide smem reduce (1 sync)
    #pragma unroll
    for (int o = 16; o > 0; o >>= 1) ss += __shfl_xor_sync(0xffffffffu, ss, o);
    __shared__ float red[8];
    __shared__ float s_inv;
    if (lane == 0) red[wq] = ss;
    __syncthreads();
    if (t == 0) {
        float tot = red[0] + red[1] + red[2] + red[3]
                  + red[4] + red[5] + red[6] + red[7];
        float inv = 1.0f / fmaxf(sqrtf(tot), 1e-12f);
        if (is_emb) g_emb_inv[row] = inv; else g_voc_inv[row] = inv;
        s_inv = inv;
    }
    __syncthreads();

    uint4 pk;
    if (is_emb) {
        ((__half2*)&pk)[0] = __floats2half2_rn(a.x, a.y);
        ((__half2*)&pk)[1] = __floats2half2_rn(a.z, a.w);
        ((__half2*)&pk)[2] = __floats2half2_rn(bb.x, bb.y);
        ((__half2*)&pk)[3] = __floats2half2_rn(bb.z, bb.w);
        *(uint4*)(g_embh + (size_t)row * DIM + t * 8) = pk;
    } else {
        float inv = s_inv;
        ((__half2*)&pk)[0] = __floats2half2_rn(a.x * inv, a.y * inv);
        ((__half2*)&pk)[1] = __floats2half2_rn(a.z * inv, a.w * inv);
        ((__half2*)&pk)[2] = __floats2half2_rn(bb.x * inv, bb.y * inv);
        ((__half2*)&pk)[3] = __floats2half2_rn(bb.z * inv, bb.w * inv);
        *(uint4*)(g_voch + (size_t)row * DIM + t * 8) = pk;
    }
}

// ---------------- f16 screen GEMM + per-row segment max ----------------------
__device__ __forceinline__ void fill_stage(uint32_t a_u32, uint32_t b_u32,
                                           int rowbase, int colbase, int kt, int tid) {
    #pragma unroll
    for (int q = 0; q < 4; q++) {                // A: 1024 x 16B chunks
        int idx = tid + q * 256;
        int r = idx >> 3, c = idx & 7;
        uint32_t dst = a_u32 + (uint32_t)(r * 128 + ((c ^ (r & 7)) << 4));
        CP16(dst, g_embh + (size_t)(rowbase + r) * DIM + kt + c * 8);
    }
    #pragma unroll
    for (int q = 0; q < 8; q++) {                // B: 2048 x 16B chunks
        int idx = tid + q * 256;
        int r = idx >> 3, c = idx & 7;
        uint32_t dst = b_u32 + (uint32_t)(r * 128 + ((c ^ (r & 7)) << 4));
        CP16(dst, g_voch + (size_t)(colbase + r) * DIM + kt + c * 8);
    }
}

// load one s-step's A/B fragments into a register buffer
#define LOAD_FRAGS(buf, s) do {                                                    \
    _Pragma("unroll")                                                              \
    for (int x = 0; x < 4; x++)                                                    \
        ldsm4(af[buf][x][0], af[buf][x][1], af[buf][x][2], af[buf][x][3],          \
              aB + a_off[x] + (uint32_t)(((((s) << 1) | a_c) ^ a_x7) << 4));       \
    _Pragma("unroll")                                                              \
    for (int jp = 0; jp < 4; jp++)                                                 \
        ldsm4(bf[buf][2*jp][0], bf[buf][2*jp][1],                                  \
              bf[buf][2*jp+1][0], bf[buf][2*jp+1][1],                              \
              bB + b_off[jp] + (uint32_t)(((((s) << 1) | b_c) ^ b_x7) << 4));      \
} while (0)

#define MMA_STEP(buf) do {                                                         \
    _Pragma("unroll")                                                              \
    for (int x = 0; x < 4; x++)                                                    \
        _Pragma("unroll")                                                          \
        for (int j2 = 0; j2 < 8; j2++)                                             \
            MMA16816F16(acc[x][j2], af[buf][x], bf[buf][j2]);                      \
} while (0)

__global__ void __launch_bounds__(256, 1) sim_gemm_kernel() {
    extern __shared__ __align__(128) char sm[];
    __shared__ float s_rmax[128][4];             // per-row, per-warp_n band max
    const uint32_t sbase = smem_u32(sm);
    const int tid  = threadIdx.x;
    const int lane = tid & 31;
    const int wid  = tid >> 5;
    const int warp_m = wid >> 2;
    const int warp_n = wid & 3;
    const int rowbase = blockIdx.x * BM;
    const int colbase = blockIdx.y * BN;

    const int a_r  = lane & 15;
    const int a_c  = lane >> 4;
    const int a_x7 = a_r & 7;
    uint32_t a_off[4];
    #pragma unroll
    for (int x = 0; x < 4; x++)
        a_off[x] = (uint32_t)((warp_m * 64 + x * 16 + a_r) * 128);

    const int b_q  = lane >> 3;
    const int b_nl = ((b_q >> 1) << 3) | (lane & 7);
    const int b_c  = b_q & 1;
    const int b_x7 = lane & 7;
    uint32_t b_off[4];
    #pragma unroll
    for (int jp = 0; jp < 4; jp++)
        b_off[jp] = (uint32_t)((warp_n * 64 + jp * 16 + b_nl) * 128);

    uint32_t acc[4][8][2];
    #pragma unroll
    for (int x = 0; x < 4; x++)
        #pragma unroll
        for (int j = 0; j < 8; j++)
            { acc[x][j][0] = 0u; acc[x][j][1] = 0u; }

    uint32_t af[2][4][4];
    uint32_t bf[2][8][2];

    #pragma unroll
    for (int p = 0; p < NSTG - 1; p++) {
        uint32_t ab = sbase + p * STG_BYTES;
        fill_stage(ab, ab + A_BYTES, rowbase, colbase, p * BK, tid);
        CP_COMMIT();
    }

    for (int i = 0; i < NKT; i++) {
        CP_WAIT(NSTG - 2);
        __syncthreads();

        const uint32_t aB = sbase + (i % NSTG) * STG_BYTES;
        const uint32_t bB = aB + A_BYTES;

        // head: issue s=0 frag loads, then cover their latency with fill issue
        LOAD_FRAGS(0, 0);

        int j = i + NSTG - 1;
        if (j < NKT) {
            uint32_t ab = sbase + (j % NSTG) * STG_BYTES;
            fill_stage(ab, ab + A_BYTES, rowbase, colbase, j * BK, tid);
        }
        CP_COMMIT();

        // software-pipelined: load s+1 while computing s
        LOAD_FRAGS(1, 1);
        MMA_STEP(0);
        LOAD_FRAGS(0, 2);
        MMA_STEP(1);
        LOAD_FRAGS(1, 3);
        MMA_STEP(0);
        MMA_STEP(1);
    }

    // epilogue: sim stores + per-(row, warp_n-band) max via hmax2 tree
    const int tr  = lane >> 2;
    const int tc4 = lane & 3;
    const int tc  = tc4 * 2;
    #pragma unroll
    for (int x = 0; x < 4; x++) {
        size_t row0 = (size_t)(rowbase + warp_m * 64 + x * 16 + tr);
        #pragma unroll
        for (int j2 = 0; j2 < 8; j2++) {
            int col = colbase + warp_n * 64 + j2 * 8 + tc;
            *(uint32_t*)(g_simh + row0 * VOCAB + col) = acc[x][j2][0];
            *(uint32_t*)(g_simh + (row0 + 8) * VOCAB + col) = acc[x][j2][1];
        }
        #pragma unroll
        for (int h = 0; h < 2; h++) {
            __half2 m01 = __hmax2(*(__half2*)&acc[x][0][h], *(__half2*)&acc[x][1][h]);
            __half2 m23 = __hmax2(*(__half2*)&acc[x][2][h], *(__half2*)&acc[x][3][h]);
            __half2 m45 = __hmax2(*(__half2*)&acc[x][4][h], *(__half2*)&acc[x][5][h]);
            __half2 m67 = __hmax2(*(__half2*)&acc[x][6][h], *(__half2*)&acc[x][7][h]);
            __half2 mm  = __hmax2(__hmax2(m01, m23), __hmax2(m45, m67));
            float mr = fmaxf(__half2float(__low2half(mm)), __half2float(__high2half(mm)));
            mr = fmaxf(mr, __shfl_xor_sync(0xffffffffu, mr, 1));
            mr = fmaxf(mr, __shfl_xor_sync(0xffffffffu, mr, 2));
            if (tc4 == 0) s_rmax[warp_m * 64 + x * 16 + h * 8 + tr][warp_n] = mr;
        }
    }
    __syncthreads();
    if (tid < BM) {
        float m = fmaxf(fmaxf(s_rmax[tid][0], s_rmax[tid][1]),
                        fmaxf(s_rmax[tid][2], s_rmax[tid][3]));
        g_rmax[(size_t)(rowbase + tid) * NCT + blockIdx.y] = m;
    }
}

// ---------------- fused: pruned top-8 screen + fp32 rescore + output --------
__global__ void __launch_bounds__(256, 2) finalize_kernel(
    const float* __restrict__ emb, const float* __restrict__ voc,
    float* __restrict__ out)
{
    int row  = blockIdx.x;
    int tid  = threadIdx.x;
    int lane = tid & 31;
    int wid  = tid >> 5;

    __shared__ float semb[DIM];
    __shared__ float smax[NCT];
    __shared__ int   ssel[NCT];
    __shared__ int   s_cnt;
    __shared__ float s_th;
    __shared__ float swv[8];
    __shared__ int   swi[8];
    __shared__ int   s_winIdx;
    __shared__ int   cidx[CAND];
    __shared__ float csim[CAND];
    __shared__ float w5[TOPK];
    __shared__ int   i5[TOPK];

    // emb row load (overlaps with segment work)
    const float4* e4 = (const float4*)(emb + (size_t)row * DIM);
    float4* s4 = (float4*)semb;
    for (int q = tid; q < DIM / 4; q += 256) s4[q] = e4[q];

    // ---- phase 0: segment maxes -> threshold = 8th largest ----
    if (tid == 0) s_cnt = 0;
    if (tid < NCT) smax[tid] = g_rmax[(size_t)row * NCT + tid];
    __syncthreads();
    if (tid < NCT) {
        float v = smax[tid];
        int rank = 0;
        for (int j = 0; j < NCT; j++) {
            float u = smax[j];
            rank += (u > v) || (u == v && j < tid);
        }
        if (rank == CAND - 1) s_th = v;    // exactly one thread has rank 7
    }
    __syncthreads();
    float th = s_th;
    if (tid < NCT && smax[tid] >= th) {
        int p = atomicAdd(&s_cnt, 1);
        ssel[p] = tid;                      // order nondet; result order-invariant
    }
    __syncthreads();
    const int K = s_cnt;                    // >= 8, expected ~8-14

    // ---- phase 1: scan only selected segments -> per-thread sorted top-8 ----
    const __half* simrow = g_simh + (size_t)row * VOCAB;
    float lv[LOCK];
    int   li[LOCK];
    #pragma unroll
    for (int i = 0; i < LOCK; i++) { lv[i] = -3e38f; li[i] = 0x7fffffff; }

    for (int v = tid; v < K * 32; v += 256) {
        int seg = v >> 5;
        int off = v & 31;
        int ct  = ssel[seg];
        uint4 w = *(const uint4*)(simrow + ct * 256 + off * 8);
        int base = ct * 256 + off * 8;
        __half2 p0 = *(__half2*)&w.x, p1 = *(__half2*)&w.y;
        __half2 p2 = *(__half2*)&w.z, p3 = *(__half2*)&w.w;
        float vals[8];
        vals[0] = __half2float(__low2half(p0)); vals[1] = __half2float(__high2half(p0));
        vals[2] = __half2float(__low2half(p1)); vals[3] = __half2float(__high2half(p1));
        vals[4] = __half2float(__low2half(p2)); vals[5] = __half2float(__high2half(p2));
        vals[6] = __half2float(__low2half(p3)); vals[7] = __half2float(__high2half(p3));
        #pragma unroll
        for (int l = 0; l < 8; l++) {
            float vv = vals[l];
            int   cc = base + l;
            if (better(vv, cc, lv[LOCK - 1], li[LOCK - 1])) {
                lv[LOCK - 1] = vv; li[LOCK - 1] = cc;
                #pragma unroll
                for (int p = LOCK - 1; p > 0; p--) {
                    if (better(lv[p], li[p], lv[p - 1], li[p - 1])) {
                        float tv = lv[p]; lv[p] = lv[p - 1]; lv[p - 1] = tv;
                        int ti = li[p]; li[p] = li[p - 1]; li[p - 1] = ti;
                    }
                }
            }
        }
    }

    // ---- phase 2: tournament merge -> global top-8 ----
    float hval = lv[0];
    int   hidx = li[0];
    int   pos  = 0;
    for (int k = 0; k < CAND; k++) {
        float v = hval; int ix = hidx;
        #pragma unroll
        for (int o = 16; o > 0; o >>= 1) {
            float v2 = __shfl_xor_sync(0xffffffffu, v, o);
            int   i2 = __shfl_xor_sync(0xffffffffu, ix, o);
            if (better(v2, i2, v, ix)) { v = v2; ix = i2; }
        }
        if (lane == 0) { swv[wid] = v; swi[wid] = ix; }
        __syncthreads();
        if (tid == 0) {
            float bv = swv[0]; int bi = swi[0];
            #pragma unroll
            for (int wq = 1; wq < 8; wq++)
                if (better(swv[wq], swi[wq], bv, bi)) { bv = swv[wq]; bi = swi[wq]; }
            cidx[k] = bi;
            s_winIdx = bi;
        }
        __syncthreads();
        int winIdx = s_winIdx;
        if (hidx == winIdx && hidx != 0x7fffffff) {
            pos++;
            hval = (pos < LOCK) ? lv[pos] : -3e38f;
            hidx = (pos < LOCK) ? li[pos] : 0x7fffffff;
        }
        __syncthreads();
    }

    // ---- phase 3: exact fp32 rescore (1 candidate per warp) ----
    float inv_e = g_emb_inv[row];
    {
        int v = cidx[wid];
        const float4* vr = (const float4*)(voc + (size_t)v * DIM);
        float acc = 0.0f;
        for (int d = lane; d < DIM / 4; d += 32) {
            float4 a = s4[d];
            float4 b = vr[d];
            acc += a.x * b.x + a.y * b.y + a.z * b.z + a.w * b.w;
        }
        #pragma unroll
        for (int o = 16; o > 0; o >>= 1) acc += __shfl_xor_sync(0xffffffffu, acc, o);
        if (lane == 0) csim[wid] = acc * inv_e * g_voc_inv[v];
    }
    __syncthreads();

    // ---- phase 4: top-5 + softmax ----
    if (tid == 0) {
        bool used[CAND];
        #pragma unroll
        for (int j = 0; j < CAND; j++) used[j] = false;
        float sv5[TOPK];
        for (int k = 0; k < TOPK; k++) {
            float best = -1e30f; int bj = -1; int bvix = 0x7fffffff;
            for (int j = 0; j < CAND; j++) {
                if (used[j]) continue;
                float v = csim[j]; int vi = cidx[j];
                if (v > best || (v == best && vi < bvix)) { best = v; bj = j; bvix = vi; }
            }
            used[bj] = true; sv5[k] = best; i5[k] = bvix;
        }
        float mx = sv5[0];
        float es[TOPK], sum = 0.0f;
        #pragma unroll
        for (int k = 0; k < TOPK; k++) { es[k] = expf((sv5[k] - mx) * TEMP); sum += es[k]; }
        #pragma unroll
        for (int k = 0; k < TOPK; k++) w5[k] = es[k] / sum;
    }
    __syncthreads();

    // ---- phase 5: projected output ----
    const float4* v0 = (const float4*)(voc + (size_t)i5[0] * DIM);
    const float4* v1 = (const float4*)(voc + (size_t)i5[1] * DIM);
    const float4* v2 = (const float4*)(voc + (size_t)i5[2] * DIM);
    const float4* v3 = (const float4*)(voc + (size_t)i5[3] * DIM);
    const float4* v4 = (const float4*)(voc + (size_t)i5[4] * DIM);
    float w0 = w5[0], w1 = w5[1], w2 = w5[2], w3 = w5[3], w4 = w5[4];
    float4* o4 = (float4*)(out + (size_t)row * DIM);

    for (int q = tid; q < DIM / 4; q += 256) {
        float4 e = s4[q];
        float4 a = v0[q], b = v1[q], c = v2[q], d = v3[q], f = v4[q];
        float4 r;
        r.x = ALPHA * e.x + (1.0f - ALPHA) * (w0 * a.x + w1 * b.x + w2 * c.x + w3 * d.x + w4 * f.x);
        r.y = ALPHA * e.y + (1.0f - ALPHA) * (w0 * a.y + w1 * b.y + w2 * c.y + w3 * d.y + w4 * f.y);
        r.z = ALPHA * e.z + (1.0f - ALPHA) * (w0 * a.z + w1 * b.z + w2 * c.z + w3 * d.z + w4 * f.z);
        r.w = ALPHA * e.w + (1.0f - ALPHA) * (w0 * a.w + w1 * b.w + w2 * c.w + w3 * d.w + w4 * f.w);
        o4[q] = r;
    }
}

// ---------------- launch -----------------------------------------------------
extern "C" void kernel_launch(void* const* d_in, const int* in_sizes, int n_in,
                              void* d_out, int out_size) {
    const float* emb = (const float*)d_in[0];
    const float* voc = (const float*)d_in[1];
    if (in_sizes[0] != NROWS * DIM) {
        emb = (const float*)d_in[1];
        voc = (const float*)d_in[0];
    }
    float* out = (float*)d_out;

    prep_kernel<<<NROWS + VOCAB, 256>>>(emb, voc);

    cudaFuncSetAttribute(sim_gemm_kernel,
                         cudaFuncAttributeMaxDynamicSharedMemorySize, GEMM_SMEM);
    dim3 grid(NROWS / BM, VOCAB / BN);   // rows-fastest: B tile L2 reuse
    sim_gemm_kernel<<<grid, 256, GEMM_SMEM>>>();

    finalize_kernel<<<NROWS, 256>>>(emb, voc, out);
}

// round 16
// speedup vs baseline: 1.0801x; 1.0801x over previous
#include <cuda_runtime.h>
#include <cuda_fp16.h>
#include <cstdint>

#define NROWS 8192
#define DIM   2048
#define VOCAB 32000
#define TOPK  5
#define CAND  8
#define LOCK  8
#define ALPHA 0.5f
#define TEMP  10.0f

// GEMM tiling (f16): CTA 128x256, k-tile 128 halfs (=256B rows, swizzled per 128B half)
#define BM    128
#define BN    256
#define BK    128
#define NKT   (DIM / BK)            // 16
#define NSTG  2
#define ROWB  256                   // bytes per smem k-row
#define NCT   (VOCAB / BN)          // 125 col tiles (segments)
#define A_BYTES (BM * ROWB)         // 32 KB
#define B_BYTES (BN * ROWB)         // 64 KB
#define STG_BYTES (A_BYTES + B_BYTES)
#define GEMM_SMEM (NSTG * STG_BYTES)   // 192 KB

// ---------------- device scratch ----------------
__device__ __half g_embh[(size_t)NROWS * DIM];
__device__ __half g_voch[(size_t)VOCAB * DIM];     // vocab * inv_norm
__device__ __half g_simh[(size_t)NROWS * VOCAB];   // f16 screen sims
__device__ float  g_rmax[(size_t)NROWS * NCT];     // per-row per-segment max
__device__ float  g_emb_inv[NROWS];
__device__ float  g_voc_inv[VOCAB];

// ---------------- helpers ----------------
__device__ __forceinline__ uint32_t smem_u32(const void* p) {
    uint32_t a;
    asm("{ .reg .u64 t; cvta.to.shared.u64 t, %1; cvt.u32.u64 %0, t; }" : "=r"(a) : "l"(p));
    return a;
}
#define CP16(dst_u32, src_ptr) \
    asm volatile("cp.async.cg.shared.global [%0], [%1], 16;" \
        :: "r"(dst_u32), "l"((unsigned long long)__cvta_generic_to_global((const void*)(src_ptr))) : "memory")
#define CP_COMMIT() asm volatile("cp.async.commit_group;" ::: "memory")
#define CP_WAIT(n)  asm volatile("cp.async.wait_group %0;" :: "n"(n) : "memory")

__device__ __forceinline__ void ldsm4(uint32_t& d0, uint32_t& d1, uint32_t& d2, uint32_t& d3,
                                      uint32_t addr) {
    asm volatile("ldmatrix.sync.aligned.m8n8.x4.shared.b16 {%0,%1,%2,%3}, [%4];"
                 : "=r"(d0), "=r"(d1), "=r"(d2), "=r"(d3) : "r"(addr));
}
// f16 inputs, f16 accumulate
#define MMA16816F16(d, a, b) \
    asm volatile("mma.sync.aligned.m16n8k16.row.col.f16.f16.f16.f16 " \
        "{%0,%1}, {%2,%3,%4,%5}, {%6,%7}, {%0,%1};" \
        : "+r"((d)[0]), "+r"((d)[1]) \
        : "r"((a)[0]), "r"((a)[1]), "r"((a)[2]), "r"((a)[3]), "r"((b)[0]), "r"((b)[1]))

// lexicographic better: higher val, tie -> smaller col (fully deterministic)
__device__ __forceinline__ bool better(float v, int c, float v2, int c2) {
    return (v > v2) || (v == v2 && c < c2);
}

// 16B-chunk address within a 256B row, swizzled per 128B half
__device__ __forceinline__ uint32_t chunk_addr(int r_times_rowb, int c, int x7) {
    return (uint32_t)(r_times_rowb + ((c >> 3) << 7) + (((c & 7) ^ x7) << 4));
}

// ---------------- fused prep: norms + f16 conversion -------------------------
// blocks [0, NROWS): emb rows; blocks [NROWS, NROWS+VOCAB): vocab rows
__global__ void __launch_bounds__(256) prep_kernel(const float* __restrict__ emb,
                                                   const float* __restrict__ voc) {
    int b = blockIdx.x;
    int t = threadIdx.x;
    int lane = t & 31;
    int wq = t >> 5;
    bool is_emb = (b < NROWS);
    int row = is_emb ? b : (b - NROWS);
    const float* src = is_emb ? (emb + (size_t)row * DIM) : (voc + (size_t)row * DIM);

    const float4* s4 = (const float4*)src;
    float4 a = s4[t * 2], bb = s4[t * 2 + 1];
    float ss = a.x*a.x + a.y*a.y + a.z*a.z + a.w*a.w
             + bb.x*bb.x + bb.y*bb.y + bb.z*bb.z + bb.w*bb.w;
    #pragma unroll
    for (int o = 16; o > 0; o >>= 1) ss += __shfl_xor_sync(0xffffffffu, ss, o);
    __shared__ float red[8];
    __shared__ float s_inv;
    if (lane == 0) red[wq] = ss;
    __syncthreads();
    if (t == 0) {
        float tot = red[0] + red[1] + red[2] + red[3]
                  + red[4] + red[5] + red[6] + red[7];
        float inv = 1.0f / fmaxf(sqrtf(tot), 1e-12f);
        if (is_emb) g_emb_inv[row] = inv; else g_voc_inv[row] = inv;
        s_inv = inv;
    }
    __syncthreads();

    uint4 pk;
    if (is_emb) {
        ((__half2*)&pk)[0] = __floats2half2_rn(a.x, a.y);
        ((__half2*)&pk)[1] = __floats2half2_rn(a.z, a.w);
        ((__half2*)&pk)[2] = __floats2half2_rn(bb.x, bb.y);
        ((__half2*)&pk)[3] = __floats2half2_rn(bb.z, bb.w);
        *(uint4*)(g_embh + (size_t)row * DIM + t * 8) = pk;
    } else {
        float inv = s_inv;
        ((__half2*)&pk)[0] = __floats2half2_rn(a.x * inv, a.y * inv);
        ((__half2*)&pk)[1] = __floats2half2_rn(a.z * inv, a.w * inv);
        ((__half2*)&pk)[2] = __floats2half2_rn(bb.x * inv, bb.y * inv);
        ((__half2*)&pk)[3] = __floats2half2_rn(bb.z * inv, bb.w * inv);
        *(uint4*)(g_voch + (size_t)row * DIM + t * 8) = pk;
    }
}

// ---------------- f16 screen GEMM + per-row segment max ----------------------
__device__ __forceinline__ void fill_stage(uint32_t a_u32, uint32_t b_u32,
                                           int rowbase, int colbase, int kt, int tid) {
    #pragma unroll
    for (int q = 0; q < 8; q++) {                // A: 2048 x 16B chunks
        int idx = tid + q * 256;
        int r = idx >> 4, c = idx & 15;
        uint32_t dst = a_u32 + chunk_addr(r * ROWB, c, r & 7);
        CP16(dst, g_embh + (size_t)(rowbase + r) * DIM + kt + c * 8);
    }
    #pragma unroll
    for (int q = 0; q < 16; q++) {               // B: 4096 x 16B chunks
        int idx = tid + q * 256;
        int r = idx >> 4, c = idx & 15;
        uint32_t dst = b_u32 + chunk_addr(r * ROWB, c, r & 7);
        CP16(dst, g_voch + (size_t)(colbase + r) * DIM + kt + c * 8);
    }
}

__global__ void __launch_bounds__(256, 1) sim_gemm_kernel() {
    extern __shared__ __align__(128) char sm[];
    __shared__ float s_rmax[128][4];             // per-row, per-warp_n band max
    const uint32_t sbase = smem_u32(sm);
    const int tid  = threadIdx.x;
    const int lane = tid & 31;
    const int wid  = tid >> 5;
    const int warp_m = wid >> 2;
    const int warp_n = wid & 3;
    const int rowbase = blockIdx.x * BM;
    const int colbase = blockIdx.y * BN;

    const int a_r  = lane & 15;
    const int a_c  = lane >> 4;
    const int a_x7 = a_r & 7;
    int a_off[4];
    #pragma unroll
    for (int x = 0; x < 4; x++)
        a_off[x] = (warp_m * 64 + x * 16 + a_r) * ROWB;

    const int b_q  = lane >> 3;
    const int b_nl = ((b_q >> 1) << 3) | (lane & 7);
    const int b_c  = b_q & 1;
    const int b_x7 = lane & 7;
    int b_off[4];
    #pragma unroll
    for (int jp = 0; jp < 4; jp++)
        b_off[jp] = (warp_n * 64 + jp * 16 + b_nl) * ROWB;

    uint32_t acc[4][8][2];
    #pragma unroll
    for (int x = 0; x < 4; x++)
        #pragma unroll
        for (int j = 0; j < 8; j++)
            { acc[x][j][0] = 0u; acc[x][j][1] = 0u; }

    // prologue: tile 0 into stage 0
    fill_stage(sbase, sbase + A_BYTES, rowbase, colbase, 0, tid);
    CP_COMMIT();

    for (int i = 0; i < NKT; i++) {
        CP_WAIT(0);
        __syncthreads();

        const uint32_t aB = sbase + (i & 1) * STG_BYTES;
        const uint32_t bB = aB + A_BYTES;

        // ---- s-step 0 first: get tensor pipe busy before issuing fills ----
        {
            uint32_t af[4][4];
            #pragma unroll
            for (int x = 0; x < 4; x++)
                ldsm4(af[x][0], af[x][1], af[x][2], af[x][3],
                      aB + chunk_addr(a_off[x], a_c, a_x7));
            uint32_t bf[8][2];
            #pragma unroll
            for (int jp = 0; jp < 4; jp++)
                ldsm4(bf[2*jp][0], bf[2*jp][1], bf[2*jp+1][0], bf[2*jp+1][1],
                      bB + chunk_addr(b_off[jp], b_c, b_x7));
            #pragma unroll
            for (int x = 0; x < 4; x++)
                #pragma unroll
                for (int j2 = 0; j2 < 8; j2++)
                    MMA16816F16(acc[x][j2], af[x], bf[j2]);
        }

        // ---- issue next-tile fill under the mma shadow ----
        int j = i + 1;
        if (j < NKT) {
            uint32_t ab = sbase + (j & 1) * STG_BYTES;
            fill_stage(ab, ab + A_BYTES, rowbase, colbase, j * BK, tid);
        }
        CP_COMMIT();

        // ---- s-steps 1..7 ----
        #pragma unroll
        for (int s = 1; s < 8; s++) {
            uint32_t af[4][4];
            #pragma unroll
            for (int x = 0; x < 4; x++)
                ldsm4(af[x][0], af[x][1], af[x][2], af[x][3],
                      aB + chunk_addr(a_off[x], (s << 1) | a_c, a_x7));
            uint32_t bf[8][2];
            #pragma unroll
            for (int jp = 0; jp < 4; jp++)
                ldsm4(bf[2*jp][0], bf[2*jp][1], bf[2*jp+1][0], bf[2*jp+1][1],
                      bB + chunk_addr(b_off[jp], (s << 1) | b_c, b_x7));
            #pragma unroll
            for (int x = 0; x < 4; x++)
                #pragma unroll
                for (int j2 = 0; j2 < 8; j2++)
                    MMA16816F16(acc[x][j2], af[x], bf[j2]);
        }
    }

    // epilogue: sim stores + per-(row, warp_n-band) max via hmax2 tree
    const int tr  = lane >> 2;
    const int tc4 = lane & 3;
    const int tc  = tc4 * 2;
    #pragma unroll
    for (int x = 0; x < 4; x++) {
        size_t row0 = (size_t)(rowbase + warp_m * 64 + x * 16 + tr);
        #pragma unroll
        for (int j2 = 0; j2 < 8; j2++) {
            int col = colbase + warp_n * 64 + j2 * 8 + tc;
            *(uint32_t*)(g_simh + row0 * VOCAB + col) = acc[x][j2][0];
            *(uint32_t*)(g_simh + (row0 + 8) * VOCAB + col) = acc[x][j2][1];
        }
        #pragma unroll
        for (int h = 0; h < 2; h++) {
            __half2 m01 = __hmax2(*(__half2*)&acc[x][0][h], *(__half2*)&acc[x][1][h]);
            __half2 m23 = __hmax2(*(__half2*)&acc[x][2][h], *(__half2*)&acc[x][3][h]);
            __half2 m45 = __hmax2(*(__half2*)&acc[x][4][h], *(__half2*)&acc[x][5][h]);
            __half2 m67 = __hmax2(*(__half2*)&acc[x][6][h], *(__half2*)&acc[x][7][h]);
            __half2 mm  = __hmax2(__hmax2(m01, m23), __hmax2(m45, m67));
            float mr = fmaxf(__half2float(__low2half(mm)), __half2float(__high2half(mm)));
            mr = fmaxf(mr, __shfl_xor_sync(0xffffffffu, mr, 1));
            mr = fmaxf(mr, __shfl_xor_sync(0xffffffffu, mr, 2));
            if (tc4 == 0) s_rmax[warp_m * 64 + x * 16 + h * 8 + tr][warp_n] = mr;
        }
    }
    __syncthreads();
    if (tid < BM) {
        float m = fmaxf(fmaxf(s_rmax[tid][0], s_rmax[tid][1]),
                        fmaxf(s_rmax[tid][2], s_rmax[tid][3]));
        g_rmax[(size_t)(rowbase + tid) * NCT + blockIdx.y] = m;
    }
}

// ---------------- fused: pruned top-8 screen + fp32 rescore + output --------
__global__ void __launch_bounds__(256, 2) finalize_kernel(
    const float* __restrict__ emb, const float* __restrict__ voc,
    float* __restrict__ out)
{
    int row  = blockIdx.x;
    int tid  = threadIdx.x;
    int lane = tid & 31;
    int wid  = tid >> 5;

    __shared__ float semb[DIM];
    __shared__ float smax[NCT];
    __shared__ int   ssel[NCT];
    __shared__ int   s_cnt;
    __shared__ float s_th;
    __shared__ float swv[8];
    __shared__ int   swi[8];
    __shared__ int   s_winIdx;
    __shared__ int   cidx[CAND];
    __shared__ float csim[CAND];
    __shared__ float w5[TOPK];
    __shared__ int   i5[TOPK];

    // emb row load (overlaps with segment work)
    const float4* e4 = (const float4*)(emb + (size_t)row * DIM);
    float4* s4 = (float4*)semb;
    for (int q = tid; q < DIM / 4; q += 256) s4[q] = e4[q];

    // ---- phase 0: segment maxes -> threshold = 8th largest ----
    if (tid == 0) s_cnt = 0;
    if (tid < NCT) smax[tid] = g_rmax[(size_t)row * NCT + tid];
    __syncthreads();
    if (tid < NCT) {
        float v = smax[tid];
        int rank = 0;
        for (int j = 0; j < NCT; j++) {
            float u = smax[j];
            rank += (u > v) || (u == v && j < tid);
        }
        if (rank == CAND - 1) s_th = v;    // exactly one thread has rank 7
    }
    __syncthreads();
    float th = s_th;
    if (tid < NCT && smax[tid] >= th) {
        int p = atomicAdd(&s_cnt, 1);
        ssel[p] = tid;                      // order nondet; result order-invariant
    }
    __syncthreads();
    const int K = s_cnt;                    // >= 8, expected ~8-14

    // ---- phase 1: scan only selected segments -> per-thread sorted top-8 ----
    const __half* simrow = g_simh + (size_t)row * VOCAB;
    float lv[LOCK];
    int   li[LOCK];
    #pragma unroll
    for (int i = 0; i < LOCK; i++) { lv[i] = -3e38f; li[i] = 0x7fffffff; }

    for (int v = tid; v < K * 32; v += 256) {
        int seg = v >> 5;
        int off = v & 31;
        int ct  = ssel[seg];
        uint4 w = *(const uint4*)(simrow + ct * 256 + off * 8);
        int base = ct * 256 + off * 8;
        __half2 p0 = *(__half2*)&w.x, p1 = *(__half2*)&w.y;
        __half2 p2 = *(__half2*)&w.z, p3 = *(__half2*)&w.w;
        float vals[8];
        vals[0] = __half2float(__low2half(p0)); vals[1] = __half2float(__high2half(p0));
        vals[2] = __half2float(__low2half(p1)); vals[3] = __half2float(__high2half(p1));
        vals[4] = __half2float(__low2half(p2)); vals[5] = __half2float(__high2half(p2));
        vals[6] = __half2float(__low2half(p3)); vals[7] = __half2float(__high2half(p3));
        #pragma unroll
        for (int l = 0; l < 8; l++) {
            float vv = vals[l];
            int   cc = base + l;
            if (better(vv, cc, lv[LOCK - 1], li[LOCK - 1])) {
                lv[LOCK - 1] = vv; li[LOCK - 1] = cc;
                #pragma unroll
                for (int p = LOCK - 1; p > 0; p--) {
                    if (better(lv[p], li[p], lv[p - 1], li[p - 1])) {
                        float tv = lv[p]; lv[p] = lv[p - 1]; lv[p - 1] = tv;
                        int ti = li[p]; li[p] = li[p - 1]; li[p - 1] = ti;
                    }
                }
            }
        }
    }

    // ---- phase 2: tournament merge -> global top-8 ----
    float hval = lv[0];
    int   hidx = li[0];
    int   pos  = 0;
    for (int k = 0; k < CAND; k++) {
        float v = hval; int ix = hidx;
        #pragma unroll
        for (int o = 16; o > 0; o >>= 1) {
            float v2 = __shfl_xor_sync(0xffffffffu, v, o);
            int   i2 = __shfl_xor_sync(0xffffffffu, ix, o);
            if (better(v2, i2, v, ix)) { v = v2; ix = i2; }
        }
        if (lane == 0) { swv[wid] = v; swi[wid] = ix; }
        __syncthreads();
        if (tid == 0) {
            float bv = swv[0]; int bi = swi[0];
            #pragma unroll
            for (int wq = 1; wq < 8; wq++)
                if (better(swv[wq], swi[wq], bv, bi)) { bv = swv[wq]; bi = swi[wq]; }
            cidx[k] = bi;
            s_winIdx = bi;
        }
        __syncthreads();
        int winIdx = s_winIdx;
        if (hidx == winIdx && hidx != 0x7fffffff) {
            pos++;
            hval = (pos < LOCK) ? lv[pos] : -3e38f;
            hidx = (pos < LOCK) ? li[pos] : 0x7fffffff;
        }
        __syncthreads();
    }

    // ---- phase 3: exact fp32 rescore (1 candidate per warp) ----
    float inv_e = g_emb_inv[row];
    {
        int v = cidx[wid];
        const float4* vr = (const float4*)(voc + (size_t)v * DIM);
        float acc = 0.0f;
        for (int d = lane; d < DIM / 4; d += 32) {
            float4 a = s4[d];
            float4 b = vr[d];
            acc += a.x * b.x + a.y * b.y + a.z * b.z + a.w * b.w;
        }
        #pragma unroll
        for (int o = 16; o > 0; o >>= 1) acc += __shfl_xor_sync(0xffffffffu, acc, o);
        if (lane == 0) csim[wid] = acc * inv_e * g_voc_inv[v];
    }
    __syncthreads();

    // ---- phase 4: top-5 + softmax ----
    if (tid == 0) {
        bool used[CAND];
        #pragma unroll
        for (int j = 0; j < CAND; j++) used[j] = false;
        float sv5[TOPK];
        for (int k = 0; k < TOPK; k++) {
            float best = -1e30f; int bj = -1; int bvix = 0x7fffffff;
            for (int j = 0; j < CAND; j++) {
                if (used[j]) continue;
                float v = csim[j]; int vi = cidx[j];
                if (v > best || (v == best && vi < bvix)) { best = v; bj = j; bvix = vi; }
            }
            used[bj] = true; sv5[k] = best; i5[k] = bvix;
        }
        float mx = sv5[0];
        float es[TOPK], sum = 0.0f;
        #pragma unroll
        for (int k = 0; k < TOPK; k++) { es[k] = expf((sv5[k] - mx) * TEMP); sum += es[k]; }
        #pragma unroll
        for (int k = 0; k < TOPK; k++) w5[k] = es[k] / sum;
    }
    __syncthreads();

    // ---- phase 5: projected output ----
    const float4* v0 = (const float4*)(voc + (size_t)i5[0] * DIM);
    const float4* v1 = (const float4*)(voc + (size_t)i5[1] * DIM);
    const float4* v2 = (const float4*)(voc + (size_t)i5[2] * DIM);
    const float4* v3 = (const float4*)(voc + (size_t)i5[3] * DIM);
    const float4* v4 = (const float4*)(voc + (size_t)i5[4] * DIM);
    float w0 = w5[0], w1 = w5[1], w2 = w5[2], w3 = w5[3], w4 = w5[4];
    float4* o4 = (float4*)(out + (size_t)row * DIM);

    for (int q = tid; q < DIM / 4; q += 256) {
        float4 e = s4[q];
        float4 a = v0[q], b = v1[q], c = v2[q], d = v3[q], f = v4[q];
        float4 r;
        r.x = ALPHA * e.x + (1.0f - ALPHA) * (w0 * a.x + w1 * b.x + w2 * c.x + w3 * d.x + w4 * f.x);
        r.y = ALPHA * e.y + (1.0f - ALPHA) * (w0 * a.y + w1 * b.y + w2 * c.y + w3 * d.y + w4 * f.y);
        r.z = ALPHA * e.z + (1.0f - ALPHA) * (w0 * a.z + w1 * b.z + w2 * c.z + w3 * d.z + w4 * f.z);
        r.w = ALPHA * e.w + (1.0f - ALPHA) * (w0 * a.w + w1 * b.w + w2 * c.w + w3 * d.w + w4 * f.w);
        o4[q] = r;
    }
}

// ---------------- launch -----------------------------------------------------
extern "C" void kernel_launch(void* const* d_in, const int* in_sizes, int n_in,
                              void* d_out, int out_size) {
    const float* emb = (const float*)d_in[0];
    const float* voc = (const float*)d_in[1];
    if (in_sizes[0] != NROWS * DIM) {
        emb = (const float*)d_in[1];
        voc = (const float*)d_in[0];
    }
    float* out = (float*)d_out;

    prep_kernel<<<NROWS + VOCAB, 256>>>(emb, voc);

    cudaFuncSetAttribute(sim_gemm_kernel,
                         cudaFuncAttributeMaxDynamicSharedMemorySize, GEMM_SMEM);
    dim3 grid(NROWS / BM, VOCAB / BN);   // rows-fastest: B tile L2 reuse
    sim_gemm_kernel<<<grid, 256, GEMM_SMEM>>>();

    finalize_kernel<<<NROWS, 256>>>(emb, voc, out);
}